// round 11
// baseline (speedup 1.0000x reference)
#include <cuda_runtime.h>
#include <stdint.h>

typedef unsigned long long ull;

// ---------- f32x2 packed-fp32 helpers ----------
__device__ __forceinline__ ull pk2(float lo, float hi) {
    ull r; asm("mov.b64 %0,{%1,%2};" : "=l"(r) : "f"(lo), "f"(hi)); return r;
}
__device__ __forceinline__ void upk2(ull v, float& lo, float& hi) {
    asm("mov.b64 {%0,%1},%2;" : "=f"(lo), "=f"(hi) : "l"(v));
}
__device__ __forceinline__ ull ffma2(ull a, ull b, ull c) {
    ull d; asm("fma.rn.f32x2 %0,%1,%2,%3;" : "=l"(d) : "l"(a), "l"(b), "l"(c)); return d;
}
__device__ __forceinline__ ull fadd2(ull a, ull b) {
    ull d; asm("add.rn.f32x2 %0,%1,%2;" : "=l"(d) : "l"(a), "l"(b)); return d;
}

// ---------- L2 sync primitives ----------
__device__ __forceinline__ ull ld_rlx(const ull* p) {
    ull v;
    asm volatile("ld.relaxed.gpu.global.u64 %0, [%1];" : "=l"(v) : "l"(p) : "memory");
    return v;
}
__device__ __forceinline__ void st_rlx(ull* p, ull v) {
    asm volatile("st.relaxed.gpu.global.u64 [%0], %1;" :: "l"(p), "l"(v) : "memory");
}
__device__ __forceinline__ unsigned ld_acq_u32(const unsigned* p) {
    unsigned v;
    asm volatile("ld.acquire.gpu.global.u32 %0, [%1];" : "=r"(v) : "l"(p) : "memory");
    return v;
}
__device__ __forceinline__ void st_rel_u32(unsigned* p, unsigned v) {
    asm volatile("st.release.gpu.global.u32 [%0], %1;" :: "l"(p), "r"(v) : "memory");
}

// ---------- problem constants ----------
#define BATCH   64
#define SEQ     2048
#define FEAT    256
#define HID     256
#define G4      1024
#define BG      4
#define NGROUP  16
#define NWORK   128
#define NHELP   20
#define THREADS 512
#define CK      16      // k per chunk (16 chunks)
#define OFFK0   64      // offloaded k range [64, 192) -> worker warps 4..11
#define OFFNK   128

// ---------- scratch ----------
__device__ ull      ht_buf[NGROUP * 2 * BG * HID];      // tagged h [grp][par][b][k]
__device__ float    xp_part[(size_t)SEQ * BATCH * G4];  // helper partials [t][b][col]
__device__ unsigned flag_buf[SEQ];

// ============================================================
__global__ void init_kernel() {
    int t = blockIdx.x * blockDim.x + threadIdx.x;
    if (t < NGROUP * 1024) {
        int grp = t >> 10, rem = t & 1023;
        ht_buf[grp * 2048 + rem] = 0ull;    // parity-0: tag 0, h=0
    }
    if (t < SEQ) flag_buf[t] = 0u;
}

// ============================================================
// Helper: 20 CTAs (threads<256) precompute xp_part over
// offK = [64,192)  (worker warps 4..11, two per SMSP).
// Helper j handles t = j, j+20, ...  Flag per t (release).
// FMA-floor-bound: ~65K cyc per t per helper -> pool cadence
// ~3.3K cyc/t, which paces the recurrence.
// ============================================================
__device__ void helper_body(int hj, const float* __restrict__ x,
                            const float* __restrict__ WX, char* smem)
{
    float (*xs)[68] = (float(*)[68])smem;                    // [128][68]  34.8 KB
    float (*ws)[64] = (float(*)[64])(smem + 128 * 68 * 4);   // [128][64]  32.8 KB

    const int tid = threadIdx.x;
    const int ty = tid >> 4, tx = tid & 15;

    for (int t = hj; t < SEQ; t += NHELP) {
        // ---- stage x-tile: 64 batches x 128 offK feats ----
#pragma unroll
        for (int it = 0; it < 8; it++) {
            int f = tid + 256 * it;           // 0..2047 float4 units
            int row = f >> 5;                 // batch 0..63
            int j = f & 31;                   // float4 within 128 k
            float4 v = *(const float4*)&x[((size_t)row * SEQ + t) * FEAT + OFFK0 + 4 * j];
            int kl = 4 * j;
            xs[kl + 0][row] = v.x; xs[kl + 1][row] = v.y;
            xs[kl + 2][row] = v.z; xs[kl + 3][row] = v.w;
        }
        for (int ct = 0; ct < 16; ct++) {
            __syncthreads();
#pragma unroll
            for (int it = 0; it < 8; it++) {
                int f2 = tid + 256 * it;      // 0..2047
                int k = f2 >> 4, c4 = f2 & 15;
                float4 v = *(const float4*)&WX[(size_t)(OFFK0 + k) * G4 + 64 * ct + 4 * c4];
                *(float4*)&ws[k][4 * c4] = v;
            }
            __syncthreads();
            ull acc[4][2];
#pragma unroll
            for (int i = 0; i < 4; i++) { acc[i][0] = pk2(0.f, 0.f); acc[i][1] = pk2(0.f, 0.f); }
#pragma unroll 16
            for (int kk = 0; kk < OFFNK; kk++) {
                float4 a4 = *(const float4*)&xs[kk][4 * ty];
                float4 b4 = *(const float4*)&ws[kk][4 * tx];
                ull b01 = pk2(b4.x, b4.y), b23 = pk2(b4.z, b4.w);
                ull am;
                am = pk2(a4.x, a4.x); acc[0][0] = ffma2(am, b01, acc[0][0]); acc[0][1] = ffma2(am, b23, acc[0][1]);
                am = pk2(a4.y, a4.y); acc[1][0] = ffma2(am, b01, acc[1][0]); acc[1][1] = ffma2(am, b23, acc[1][1]);
                am = pk2(a4.z, a4.z); acc[2][0] = ffma2(am, b01, acc[2][0]); acc[2][1] = ffma2(am, b23, acc[2][1]);
                am = pk2(a4.w, a4.w); acc[3][0] = ffma2(am, b01, acc[3][0]); acc[3][1] = ffma2(am, b23, acc[3][1]);
            }
            size_t base = ((size_t)t * BATCH + 4 * ty) * G4 + 64 * ct + 4 * tx;
#pragma unroll
            for (int i = 0; i < 4; i++) {
                float4 o;
                upk2(acc[i][0], o.x, o.y);
                upk2(acc[i][1], o.z, o.w);
                *(float4*)&xp_part[base + (size_t)i * G4] = o;
            }
        }
        __syncthreads();
        if (tid == 0) st_rel_u32(&flag_buf[t], 1u);
        __syncthreads();
    }
}

// ============================================================
// Worker: 128 CTAs x 512 threads (16 warps, 4/SMSP).
// Warp w owns K-chunk [16w,16w+16): WH slice in 64 regs/thread,
// polls its own producer slots (2/lane), hd/xd warp-private.
// Warps 4-11 skip xp (helpers cover k in [64,192) — 2 per SMSP,
// so FMA max/SMSP drops to 4h+2xp = 1536 cyc).
// ============================================================
__device__ __forceinline__ float fsig(float x) {
    return __fdividef(1.0f, 1.0f + __expf(-x));
}
__device__ __forceinline__ float ftanh(float x) { return 2.0f * fsig(2.0f * x) - 1.0f; }

__device__ void worker_body(float* __restrict__ out,
                            const float* __restrict__ x,
                            const float* __restrict__ WX,
                            const float* __restrict__ WH,
                            const float* __restrict__ BX,
                            const float* __restrict__ BH,
                            long long out_size, char* smem)
{
    ulonglong2* wx_u2   = (ulonglong2*)smem;                      // [256][32]  128 KB
    ull*        hd      = (ull*)(smem + 131072);                  // [256][4]     8 KB
    ull*        xd      = (ull*)(smem + 131072 + 8192);           // [256][4]     8 KB
    ulonglong2* red     = (ulonglong2*)(smem + 131072 + 16384);   // [2][4][16][32] 64 KB
    float*      gates_s = (float*)(smem + 131072 + 16384 + 65536);// [4][128]     2 KB

    const int tid = threadIdx.x;
    const int grp = blockIdx.x >> 3;
    const int r   = blockIdx.x & 7;
    const int batch0 = grp * BG;

    const int w    = tid >> 5;           // chunk 0..15
    const int lane = tid & 31;
    const int cq   = lane;
    const int kbase = CK * w;
    const int kown  = kbase + (lane & 15);
    const int bb    = (lane >> 4) << 1;  // batch pair base: 0 or 2
    const bool xact = (w < 4) | (w > 11); // warps 4-11 offloaded (2 per SMSP)
    const int rb = tid >> 5;             // act batch (tid<128)
    const int rc = lane;

    // ---- WX slice into SMEM, pre-packed ----
    for (int idx = tid; idx < 8192; idx += THREADS) {
        int f = idx >> 5, ci = idx & 31;
        int gcl = (ci >> 3) * HID + 32 * r + ((4 * ci) & 31);
        float4 w4 = *(const float4*)&WX[(size_t)f * G4 + gcl];
        wx_u2[idx] = make_ulonglong2(pk2(w4.x, w4.y), pk2(w4.z, w4.w));
    }

    // ---- WH chunk into registers (64 regs) ----
    ull wA[CK], wB[CK];
    {
        const int gc = (cq >> 3) * HID + 32 * r + ((4 * cq) & 31);
        const float* wp = WH + (size_t)kbase * G4 + gc;
#pragma unroll
        for (int kk = 0; kk < CK; kk++) {
            float4 w4 = *(const float4*)(wp + (size_t)kk * G4);
            wA[kk] = pk2(w4.x, w4.y);
            wB[kk] = pk2(w4.z, w4.w);
        }
    }

    // ---- bias + gate-col for act threads ----
    ull biasA = pk2(0.f, 0.f), biasB = biasA;
    int gcol = 0;
    if (tid < 128) {
        gcol = (rc >> 3) * HID + 32 * r + ((4 * rc) & 31);
        float4 bx4 = *(const float4*)&BX[gcol];
        float4 bh4 = *(const float4*)&BH[gcol];
        biasA = pk2(bx4.x + bh4.x, bx4.y + bh4.y);
        biasB = pk2(bx4.z + bh4.z, bx4.w + bh4.w);
    }

    // ---- x: this thread feeds (kown, bb) and (kown, bb+1) ----
    const float* xb0 = x + ((size_t)(batch0 + bb) * SEQ) * FEAT + kown;
    const float* xb1 = xb0 + (size_t)SEQ * FEAT;
    float xr0 = 0.f, xr1 = 0.f;
    if (xact) {
        float a0 = xb0[0], a1 = xb1[0];          // x(0)
        xd[kown * BG + bb]     = pk2(a0, a0);
        xd[kown * BG + bb + 1] = pk2(a1, a1);
        xr0 = xb0[FEAT];                          // x(1)
        xr1 = xb1[FEAT];
    }
    __syncthreads();

    ull* htg = &ht_buf[(size_t)grp * 2048];       // [par][b][k]

    ull a00, a01, a10, a11, a20, a21, a30, a31;
    a00 = a01 = a10 = a11 = a20 = a21 = a30 = a31 = pk2(0.f, 0.f);
    if (xact) {   // prologue xp-GEMM(0)
        const ull* xp_ = xd + kbase * BG;
        const ulonglong2* wp = wx_u2 + kbase * 32 + cq;
#pragma unroll
        for (int kk = 0; kk < CK; kk++) {
            ulonglong2 d0 = *(const ulonglong2*)(xp_ + kk * 4);
            ulonglong2 d1 = *(const ulonglong2*)(xp_ + kk * 4 + 2);
            ulonglong2 w2 = wp[kk * 32];
            a00 = ffma2(d0.x, w2.x, a00); a01 = ffma2(d0.x, w2.y, a01);
            a10 = ffma2(d0.y, w2.x, a10); a11 = ffma2(d0.y, w2.y, a11);
            a20 = ffma2(d1.x, w2.x, a20); a21 = ffma2(d1.x, w2.y, a21);
            a30 = ffma2(d1.y, w2.x, a30); a31 = ffma2(d1.y, w2.y, a31);
        }
    }

    // ---- speculative preload t=0 (parity-0 zeroed: guaranteed hit) ----
    ull sv0 = ld_rlx(htg + bb * 256 + kown);
    ull sv1 = ld_rlx(htg + (bb + 1) * 256 + kown);

    float cstate = 0.0f, hlast = 0.0f;

    for (int t = 0; t < SEQ; t++) {
        const int par = t & 1;

        // ---- stage x(t+1) (warp-private xd) ----
        if (xact) {
            xd[kown * BG + bb]     = pk2(xr0, xr0);
            xd[kown * BG + bb + 1] = pk2(xr1, xr1);
        }

        // ---- poll own slots; pack hd (warp-private) ----
        {
            const ull* sp0 = htg + (size_t)par * 1024 + bb * 256 + kown;
            const unsigned tg = (unsigned)t;
            while (((unsigned)(sv0 >> 32) != tg) | ((unsigned)(sv1 >> 32) != tg)) {
                sv0 = ld_rlx(sp0); sv1 = ld_rlx(sp0 + 256);
            }
            float h0 = __uint_as_float((unsigned)sv0);
            float h1 = __uint_as_float((unsigned)sv1);
            hd[kown * BG + bb]     = pk2(h0, h0);
            hd[kown * BG + bb + 1] = pk2(h1, h1);
        }
        __syncwarp();

        // ---- flag-gated xp_part prefetch (act threads; hides under h-GEMM) ----
        float4 xpp = make_float4(0.f, 0.f, 0.f, 0.f);
        if (tid < 128) {
            while (ld_acq_u32(&flag_buf[t]) == 0u) { }
            xpp = __ldcg((const float4*)&xp_part[((size_t)t * BATCH + batch0 + rb) * G4 + gcol]);
        }

        // ---- h-GEMM chunk (accumulates onto xp-partials) ----
        {
            const ull* hp = hd + kbase * BG;
#pragma unroll
            for (int kk = 0; kk < CK; kk++) {
                ulonglong2 d0 = *(const ulonglong2*)(hp + kk * 4);
                ulonglong2 d1 = *(const ulonglong2*)(hp + kk * 4 + 2);
                a00 = ffma2(d0.x, wA[kk], a00); a01 = ffma2(d0.x, wB[kk], a01);
                a10 = ffma2(d0.y, wA[kk], a10); a11 = ffma2(d0.y, wB[kk], a11);
                a20 = ffma2(d1.x, wA[kk], a20); a21 = ffma2(d1.x, wB[kk], a21);
                a30 = ffma2(d1.y, wA[kk], a30); a31 = ffma2(d1.y, wB[kk], a31);
            }
        }
        {   // stage: red[par][b][w][cq]
            ulonglong2* rp = red + (size_t)par * 2048;
            rp[(0 * 16 + w) * 32 + cq] = make_ulonglong2(a00, a01);
            rp[(1 * 16 + w) * 32 + cq] = make_ulonglong2(a10, a11);
            rp[(2 * 16 + w) * 32 + cq] = make_ulonglong2(a20, a21);
            rp[(3 * 16 + w) * 32 + cq] = make_ulonglong2(a30, a31);
        }
        __syncthreads();   // the ONE CTA-wide sync per step

        // ---- reduce 16 partials (+bias +xp_part) -> act -> publish ----
        if (tid < 128) {
            const ulonglong2* q = red + (size_t)par * 2048 + rb * 512;
            ull s0 = fadd2(biasA, pk2(xpp.x, xpp.y));
            ull s1 = fadd2(biasB, pk2(xpp.z, xpp.w));
#pragma unroll
            for (int j = 0; j < 16; j++) {
                ulonglong2 v = q[j * 32 + rc];
                s0 = fadd2(s0, v.x);
                s1 = fadd2(s1, v.y);
            }
            float g0, g1, g2, g3;
            upk2(s0, g0, g1); upk2(s1, g2, g3);
            *(float4*)&gates_s[rb * 128 + 4 * rc] = make_float4(g0, g1, g2, g3);
        }
        __syncwarp();
        if (tid < 128) {
            float gi = gates_s[rb * 128 +       rc];
            float gf = gates_s[rb * 128 +  32 + rc];
            float gg = gates_s[rb * 128 +  64 + rc];
            float go = gates_s[rb * 128 +  96 + rc];
            float i_ = fsig(gi), f_ = fsig(gf), g_ = ftanh(gg), o_ = fsig(go);
            cstate = f_ * cstate + i_ * g_;
            float h_ = o_ * ftanh(cstate);
            hlast = h_;
            const int kidx = 32 * r + rc;
            ull pv = (ull)__float_as_uint(h_) | ((ull)(unsigned)(t + 1) << 32);
            st_rlx(htg + (size_t)(par ^ 1) * 1024 + rb * 256 + kidx, pv);
            out[((size_t)(batch0 + rb) * SEQ + t) * HID + kidx] = h_;
        }

        // ---- prefetch x(t+2) ----
        if (xact) {
            size_t tn = (size_t)((t + 2 < SEQ) ? (t + 2) : t) * FEAT;
            xr0 = xb0[tn];
            xr1 = xb1[tn];
        }

        // ---- xp-GEMM(t+1) with mid-point speculative polls ----
        a00 = a01 = a10 = a11 = a20 = a21 = a30 = a31 = pk2(0.f, 0.f);
        if (xact) {
            const ull* xp_ = xd + kbase * BG;
            const ulonglong2* wp = wx_u2 + kbase * 32 + cq;
#pragma unroll
            for (int kk = 0; kk < 8; kk++) {
                ulonglong2 d0 = *(const ulonglong2*)(xp_ + kk * 4);
                ulonglong2 d1 = *(const ulonglong2*)(xp_ + kk * 4 + 2);
                ulonglong2 w2 = wp[kk * 32];
                a00 = ffma2(d0.x, w2.x, a00); a01 = ffma2(d0.x, w2.y, a01);
                a10 = ffma2(d0.y, w2.x, a10); a11 = ffma2(d0.y, w2.y, a11);
                a20 = ffma2(d1.x, w2.x, a20); a21 = ffma2(d1.x, w2.y, a21);
                a30 = ffma2(d1.y, w2.x, a30); a31 = ffma2(d1.y, w2.y, a31);
            }
            {   // speculative polls for t+1
                const ull* sp = htg + (size_t)(par ^ 1) * 1024 + bb * 256 + kown;
                sv0 = ld_rlx(sp); sv1 = ld_rlx(sp + 256);
            }
#pragma unroll
            for (int kk = 8; kk < CK; kk++) {
                ulonglong2 d0 = *(const ulonglong2*)(xp_ + kk * 4);
                ulonglong2 d1 = *(const ulonglong2*)(xp_ + kk * 4 + 2);
                ulonglong2 w2 = wp[kk * 32];
                a00 = ffma2(d0.x, w2.x, a00); a01 = ffma2(d0.x, w2.y, a01);
                a10 = ffma2(d0.y, w2.x, a10); a11 = ffma2(d0.y, w2.y, a11);
                a20 = ffma2(d1.x, w2.x, a20); a21 = ffma2(d1.x, w2.y, a21);
                a30 = ffma2(d1.y, w2.x, a30); a31 = ffma2(d1.y, w2.y, a31);
            }
        } else {
            const ull* sp = htg + (size_t)(par ^ 1) * 1024 + bb * 256 + kown;
            sv0 = ld_rlx(sp); sv1 = ld_rlx(sp + 256);
        }
    }

    if (tid < 128 && out_size >= (long long)BATCH * SEQ * HID + BATCH * HID) {
        out[(size_t)BATCH * SEQ * HID + (size_t)(batch0 + rb) * HID + 32 * r + rc] = hlast;
    }
}

// ============================================================
__global__ __launch_bounds__(THREADS, 1)
void lstm_kernel(float* __restrict__ out,
                 const float* __restrict__ x,
                 const float* __restrict__ WX,
                 const float* __restrict__ WH,
                 const float* __restrict__ BX,
                 const float* __restrict__ BH,
                 long long out_size)
{
    extern __shared__ char smem[];
    if (blockIdx.x >= NWORK) {
        if (threadIdx.x < 256) helper_body(blockIdx.x - NWORK, x, WX, smem);
    } else {
        worker_body(out, x, WX, WH, BX, BH, out_size, smem);
    }
}

// ============================================================
extern "C" void kernel_launch(void* const* d_in, const int* in_sizes, int n_in,
                              void* d_out, int out_size)
{
    const float* x  = (const float*)d_in[0];
    const float* WX = (const float*)d_in[1];
    const float* WH = (const float*)d_in[2];
    const float* BX = (const float*)d_in[3];
    const float* BH = (const float*)d_in[4];
    float* out = (float*)d_out;

    const size_t smem_bytes = 131072 + 16384 + 65536 + 2048;  // 215040
    cudaFuncSetAttribute(lstm_kernel, cudaFuncAttributeMaxDynamicSharedMemorySize,
                         (int)smem_bytes);

    init_kernel<<<64, 256>>>();
    lstm_kernel<<<NWORK + NHELP, THREADS, smem_bytes>>>(
        out, x, WX, WH, BX, BH, (long long)out_size);
}

// round 12
// speedup vs baseline: 1.4285x; 1.4285x over previous
#include <cuda_runtime.h>
#include <stdint.h>

typedef unsigned long long ull;

// ---------- f32x2 packed-fp32 helpers ----------
__device__ __forceinline__ ull pk2(float lo, float hi) {
    ull r; asm("mov.b64 %0,{%1,%2};" : "=l"(r) : "f"(lo), "f"(hi)); return r;
}
__device__ __forceinline__ void upk2(ull v, float& lo, float& hi) {
    asm("mov.b64 {%0,%1},%2;" : "=f"(lo), "=f"(hi) : "l"(v));
}
__device__ __forceinline__ ull ffma2(ull a, ull b, ull c) {
    ull d; asm("fma.rn.f32x2 %0,%1,%2,%3;" : "=l"(d) : "l"(a), "l"(b), "l"(c)); return d;
}
__device__ __forceinline__ ull fadd2(ull a, ull b) {
    ull d; asm("add.rn.f32x2 %0,%1,%2;" : "=l"(d) : "l"(a), "l"(b)); return d;
}

// ---------- L2 sync primitives ----------
__device__ __forceinline__ ull ld_rlx(const ull* p) {
    ull v;
    asm volatile("ld.relaxed.gpu.global.u64 %0, [%1];" : "=l"(v) : "l"(p) : "memory");
    return v;
}
__device__ __forceinline__ void st_rlx(ull* p, ull v) {
    asm volatile("st.relaxed.gpu.global.u64 [%0], %1;" :: "l"(p), "l"(v) : "memory");
}
__device__ __forceinline__ unsigned ld_acq_u32(const unsigned* p) {
    unsigned v;
    asm volatile("ld.acquire.gpu.global.u32 %0, [%1];" : "=r"(v) : "l"(p) : "memory");
    return v;
}
__device__ __forceinline__ void st_rel_u32(unsigned* p, unsigned v) {
    asm volatile("st.release.gpu.global.u32 [%0], %1;" :: "l"(p), "r"(v) : "memory");
}

// ---------- problem constants ----------
#define BATCH   64
#define SEQ     2048
#define FEAT    256
#define HID     256
#define G4      1024
#define BG      4
#define NGROUP  16
#define NWORK   128
#define NHELP   20
#define THREADS 512
#define CK      16      // k per chunk; 16 chunks; warps 0-3's chunks (k<64) offloaded

// ---------- scratch ----------
__device__ ull      ht_buf[NGROUP * 2 * BG * HID];      // tagged h [grp][par][b][k]
__device__ float    xp_part[(size_t)SEQ * BATCH * G4];  // helper partials [t][b][col]
__device__ unsigned flag_buf[SEQ];

// ============================================================
__global__ void init_kernel() {
    int t = blockIdx.x * blockDim.x + threadIdx.x;
    if (t < NGROUP * 1024) {
        int grp = t >> 10, rem = t & 1023;
        ht_buf[grp * 2048 + rem] = 0ull;    // parity-0: tag 0, h=0
    }
    if (t < SEQ) flag_buf[t] = 0u;
}

// ============================================================
// Helper: 20 CTAs (threads<256) precompute xp_part over
// offK = [0,64)  (worker act-warps 0..3). Proven-sustainable load.
// ============================================================
__device__ void helper_body(int hj, const float* __restrict__ x,
                            const float* __restrict__ WX, char* smem)
{
    float (*xs)[68] = (float(*)[68])smem;
    float (*ws)[64] = (float(*)[64])(smem + 64 * 68 * 4);

    const int tid = threadIdx.x;
    const int ty = tid >> 4, tx = tid & 15;

    for (int t = hj; t < SEQ; t += NHELP) {
#pragma unroll
        for (int it = 0; it < 4; it++) {
            int f = tid + 256 * it;           // 0..1023
            int row = f >> 4, j = f & 15;
            float4 v = *(const float4*)&x[((size_t)row * SEQ + t) * FEAT + 4 * j];
            int kl = 4 * j;
            xs[kl + 0][row] = v.x; xs[kl + 1][row] = v.y;
            xs[kl + 2][row] = v.z; xs[kl + 3][row] = v.w;
        }
        for (int ct = 0; ct < 16; ct++) {
            __syncthreads();
#pragma unroll
            for (int it = 0; it < 4; it++) {
                int f2 = tid + 256 * it;
                int k = f2 >> 4, c4 = f2 & 15;
                float4 v = *(const float4*)&WX[(size_t)k * G4 + 64 * ct + 4 * c4];
                *(float4*)&ws[k][4 * c4] = v;
            }
            __syncthreads();
            ull acc[4][2];
#pragma unroll
            for (int i = 0; i < 4; i++) { acc[i][0] = pk2(0.f, 0.f); acc[i][1] = pk2(0.f, 0.f); }
#pragma unroll 16
            for (int kk = 0; kk < 64; kk++) {
                float4 a4 = *(const float4*)&xs[kk][4 * ty];
                float4 b4 = *(const float4*)&ws[kk][4 * tx];
                ull b01 = pk2(b4.x, b4.y), b23 = pk2(b4.z, b4.w);
                ull am;
                am = pk2(a4.x, a4.x); acc[0][0] = ffma2(am, b01, acc[0][0]); acc[0][1] = ffma2(am, b23, acc[0][1]);
                am = pk2(a4.y, a4.y); acc[1][0] = ffma2(am, b01, acc[1][0]); acc[1][1] = ffma2(am, b23, acc[1][1]);
                am = pk2(a4.z, a4.z); acc[2][0] = ffma2(am, b01, acc[2][0]); acc[2][1] = ffma2(am, b23, acc[2][1]);
                am = pk2(a4.w, a4.w); acc[3][0] = ffma2(am, b01, acc[3][0]); acc[3][1] = ffma2(am, b23, acc[3][1]);
            }
            size_t base = ((size_t)t * BATCH + 4 * ty) * G4 + 64 * ct + 4 * tx;
#pragma unroll
            for (int i = 0; i < 4; i++) {
                float4 o;
                upk2(acc[i][0], o.x, o.y);
                upk2(acc[i][1], o.z, o.w);
                *(float4*)&xp_part[base + (size_t)i * G4] = o;
            }
        }
        __syncthreads();
        if (tid == 0) st_rel_u32(&flag_buf[t], 1u);
        __syncthreads();
    }
}

// ============================================================
// Worker: 128 CTAs x 512 threads, WARP-SPECIALIZED step pipeline.
// Warps 0-3 (act): poll, h-GEMM k<64, stage, bar.sync, reduce+act+
//   publish (their xp offloaded to helpers).
// Warps 4-15 (gemm): poll, h-GEMM, stage, bar.ARRIVE (non-blocking),
//   then x-stage + xp-GEMM(t+1) + spec polls — overlaps act phase.
// red triple-buffered (t%3): group publish/poll chain bounds gemm
// warps to <= act+2 steps, so 3 buffers suffice; no __syncthreads
// in the loop.
// ============================================================
__device__ __forceinline__ float fsig(float x) {
    return __fdividef(1.0f, 1.0f + __expf(-x));
}
__device__ __forceinline__ float ftanh(float x) { return 2.0f * fsig(2.0f * x) - 1.0f; }

__device__ void worker_body(float* __restrict__ out,
                            const float* __restrict__ x,
                            const float* __restrict__ WX,
                            const float* __restrict__ WH,
                            const float* __restrict__ BX,
                            const float* __restrict__ BH,
                            long long out_size, char* smem)
{
    ulonglong2* wx_u2   = (ulonglong2*)smem;                 // [192][32] k=64..255  96 KB
    ull*        hd      = (ull*)(smem + 98304);              // [256][4]              8 KB
    ull*        xd      = (ull*)(smem + 106496);             // [256][4]              8 KB
    ulonglong2* red     = (ulonglong2*)(smem + 114688);      // [3][4][16][32]       96 KB
    float*      gates_s = (float*)(smem + 212992);           // [4][128]              2 KB

    const int tid = threadIdx.x;
    const int grp = blockIdx.x >> 3;
    const int r   = blockIdx.x & 7;
    const int batch0 = grp * BG;

    const int w    = tid >> 5;           // chunk 0..15
    const int lane = tid & 31;
    const int cq   = lane;
    const int kbase = CK * w;
    const int kown  = kbase + (lane & 15);
    const int bb    = (lane >> 4) << 1;
    const bool isact = (w < 4);          // warps 0-3: act duty; xp offloaded

    // ---- WX slice (k 64..255) into SMEM, pre-packed ----
    for (int idx = tid; idx < 192 * 32; idx += THREADS) {
        int f = idx >> 5, ci = idx & 31;
        int gcl = (ci >> 3) * HID + 32 * r + ((4 * ci) & 31);
        float4 w4 = *(const float4*)&WX[(size_t)(64 + f) * G4 + gcl];
        wx_u2[idx] = make_ulonglong2(pk2(w4.x, w4.y), pk2(w4.z, w4.w));
    }

    // ---- WH chunk into registers (all 16 warps) ----
    ull wA[CK], wB[CK];
    {
        const int gc = (cq >> 3) * HID + 32 * r + ((4 * cq) & 31);
        const float* wp = WH + (size_t)kbase * G4 + gc;
#pragma unroll
        for (int kk = 0; kk < CK; kk++) {
            float4 w4 = *(const float4*)(wp + (size_t)kk * G4);
            wA[kk] = pk2(w4.x, w4.y);
            wB[kk] = pk2(w4.z, w4.w);
        }
    }

    // ---- bias + gate-col (act warps) ----
    ull biasA = pk2(0.f, 0.f), biasB = biasA;
    int gcol = 0;
    if (isact) {
        gcol = (lane >> 3) * HID + 32 * r + ((4 * lane) & 31);
        float4 bx4 = *(const float4*)&BX[gcol];
        float4 bh4 = *(const float4*)&BH[gcol];
        biasA = pk2(bx4.x + bh4.x, bx4.y + bh4.y);
        biasB = pk2(bx4.z + bh4.z, bx4.w + bh4.w);
    }

    // ---- x feeds (gemm warps only; k 64..255) ----
    const float* xb0 = x + ((size_t)(batch0 + bb) * SEQ) * FEAT + kown;
    const float* xb1 = xb0 + (size_t)SEQ * FEAT;
    float xr0 = 0.f, xr1 = 0.f;
    if (!isact) {
        float a0 = xb0[0], a1 = xb1[0];          // x(0)
        xd[kown * BG + bb]     = pk2(a0, a0);
        xd[kown * BG + bb + 1] = pk2(a1, a1);
        xr0 = xb0[FEAT];                          // x(1)
        xr1 = xb1[FEAT];
    }
    __syncthreads();   // wx_s + xd(0) visible

    ull* htg = &ht_buf[(size_t)grp * 2048];       // [par][b][k]

    ull a00, a01, a10, a11, a20, a21, a30, a31;
    a00 = a01 = a10 = a11 = a20 = a21 = a30 = a31 = pk2(0.f, 0.f);
    if (!isact) {   // prologue xp-GEMM(0)
        const ull* xp_ = xd + kbase * BG;
        const ulonglong2* wp = wx_u2 + (kbase - 64) * 32 + cq;
#pragma unroll
        for (int kk = 0; kk < CK; kk++) {
            ulonglong2 d0 = *(const ulonglong2*)(xp_ + kk * 4);
            ulonglong2 d1 = *(const ulonglong2*)(xp_ + kk * 4 + 2);
            ulonglong2 w2 = wp[kk * 32];
            a00 = ffma2(d0.x, w2.x, a00); a01 = ffma2(d0.x, w2.y, a01);
            a10 = ffma2(d0.y, w2.x, a10); a11 = ffma2(d0.y, w2.y, a11);
            a20 = ffma2(d1.x, w2.x, a20); a21 = ffma2(d1.x, w2.y, a21);
            a30 = ffma2(d1.y, w2.x, a30); a31 = ffma2(d1.y, w2.y, a31);
        }
    }

    // ---- speculative preload t=0 (parity-0 zeroed: guaranteed hit) ----
    ull sv0 = ld_rlx(htg + bb * 256 + kown);
    ull sv1 = ld_rlx(htg + (bb + 1) * 256 + kown);

    float cstate = 0.0f, hlast = 0.0f;
    int p3 = 0;

    for (int t = 0; t < SEQ; t++) {
        const int par = t & 1;

        // ---- poll own slots; pack hd (warp-private) ----
        {
            const ull* sp0 = htg + (size_t)par * 1024 + bb * 256 + kown;
            const unsigned tg = (unsigned)t;
            while (((unsigned)(sv0 >> 32) != tg) | ((unsigned)(sv1 >> 32) != tg)) {
                sv0 = ld_rlx(sp0); sv1 = ld_rlx(sp0 + 256);
            }
            float h0 = __uint_as_float((unsigned)sv0);
            float h1 = __uint_as_float((unsigned)sv1);
            hd[kown * BG + bb]     = pk2(h0, h0);
            hd[kown * BG + bb + 1] = pk2(h1, h1);
        }
        __syncwarp();

        // ---- act warps: flag-gated xp_part prefetch (hides under h-GEMM) ----
        float4 xpp = make_float4(0.f, 0.f, 0.f, 0.f);
        if (isact) {
            while (ld_acq_u32(&flag_buf[t]) == 0u) { }
            xpp = __ldcg((const float4*)&xp_part[((size_t)t * BATCH + batch0 + w) * G4 + gcol]);
            a00 = a01 = a10 = a11 = a20 = a21 = a30 = a31 = pk2(0.f, 0.f);
        }

        // ---- h-GEMM chunk (all 16 warps) ----
        {
            const ull* hp = hd + kbase * BG;
#pragma unroll
            for (int kk = 0; kk < CK; kk++) {
                ulonglong2 d0 = *(const ulonglong2*)(hp + kk * 4);
                ulonglong2 d1 = *(const ulonglong2*)(hp + kk * 4 + 2);
                a00 = ffma2(d0.x, wA[kk], a00); a01 = ffma2(d0.x, wB[kk], a01);
                a10 = ffma2(d0.y, wA[kk], a10); a11 = ffma2(d0.y, wB[kk], a11);
                a20 = ffma2(d1.x, wA[kk], a20); a21 = ffma2(d1.x, wB[kk], a21);
                a30 = ffma2(d1.y, wA[kk], a30); a31 = ffma2(d1.y, wB[kk], a31);
            }
        }
        {   // stage: red[p3][b][w][cq]
            ulonglong2* rp = red + (size_t)p3 * 2048;
            rp[(0 * 16 + w) * 32 + cq] = make_ulonglong2(a00, a01);
            rp[(1 * 16 + w) * 32 + cq] = make_ulonglong2(a10, a11);
            rp[(2 * 16 + w) * 32 + cq] = make_ulonglong2(a20, a21);
            rp[(3 * 16 + w) * 32 + cq] = make_ulonglong2(a30, a31);
        }
        __syncwarp();   // all lanes past h-GEMM reads before next hd/xd writes

        if (!isact) {
            // ---- signal staging done; do NOT wait for act phase ----
            asm volatile("bar.arrive 1, 512;" ::: "memory");

            // ---- stage x(t+1), prefetch x(t+2) ----
            xd[kown * BG + bb]     = pk2(xr0, xr0);
            xd[kown * BG + bb + 1] = pk2(xr1, xr1);
            __syncwarp();
            {
                size_t tn = (size_t)((t + 2 < SEQ) ? (t + 2) : t) * FEAT;
                xr0 = xb0[tn];
                xr1 = xb1[tn];
            }

            // ---- xp-GEMM(t+1) with mid-point speculative polls ----
            a00 = a01 = a10 = a11 = a20 = a21 = a30 = a31 = pk2(0.f, 0.f);
            const ull* xp_ = xd + kbase * BG;
            const ulonglong2* wp = wx_u2 + (kbase - 64) * 32 + cq;
#pragma unroll
            for (int kk = 0; kk < 8; kk++) {
                ulonglong2 d0 = *(const ulonglong2*)(xp_ + kk * 4);
                ulonglong2 d1 = *(const ulonglong2*)(xp_ + kk * 4 + 2);
                ulonglong2 w2 = wp[kk * 32];
                a00 = ffma2(d0.x, w2.x, a00); a01 = ffma2(d0.x, w2.y, a01);
                a10 = ffma2(d0.y, w2.x, a10); a11 = ffma2(d0.y, w2.y, a11);
                a20 = ffma2(d1.x, w2.x, a20); a21 = ffma2(d1.x, w2.y, a21);
                a30 = ffma2(d1.y, w2.x, a30); a31 = ffma2(d1.y, w2.y, a31);
            }
            {   // speculative polls for t+1
                const ull* sp = htg + (size_t)(par ^ 1) * 1024 + bb * 256 + kown;
                sv0 = ld_rlx(sp); sv1 = ld_rlx(sp + 256);
            }
#pragma unroll
            for (int kk = 8; kk < CK; kk++) {
                ulonglong2 d0 = *(const ulonglong2*)(xp_ + kk * 4);
                ulonglong2 d1 = *(const ulonglong2*)(xp_ + kk * 4 + 2);
                ulonglong2 w2 = wp[kk * 32];
                a00 = ffma2(d0.x, w2.x, a00); a01 = ffma2(d0.x, w2.y, a01);
                a10 = ffma2(d0.y, w2.x, a10); a11 = ffma2(d0.y, w2.y, a11);
                a20 = ffma2(d1.x, w2.x, a20); a21 = ffma2(d1.x, w2.y, a21);
                a30 = ffma2(d1.y, w2.x, a30); a31 = ffma2(d1.y, w2.y, a31);
            }
        } else {
            // ---- wait for all 16 stagings ----
            asm volatile("bar.sync 1, 512;" ::: "memory");

            // ---- reduce 16 partials (+bias +xp_part) ----
            const ulonglong2* q = red + (size_t)p3 * 2048 + w * 512;
            ull s0 = fadd2(biasA, pk2(xpp.x, xpp.y));
            ull s1 = fadd2(biasB, pk2(xpp.z, xpp.w));
#pragma unroll
            for (int j = 0; j < 16; j++) {
                ulonglong2 v = q[j * 32 + lane];
                s0 = fadd2(s0, v.x);
                s1 = fadd2(s1, v.y);
            }
            float g0, g1, g2, g3;
            upk2(s0, g0, g1); upk2(s1, g2, g3);
            *(float4*)&gates_s[w * 128 + 4 * lane] = make_float4(g0, g1, g2, g3);
            __syncwarp();

            // ---- act + publish + archive ----
            float gi = gates_s[w * 128 +       lane];
            float gf = gates_s[w * 128 +  32 + lane];
            float gg = gates_s[w * 128 +  64 + lane];
            float go = gates_s[w * 128 +  96 + lane];
            float i_ = fsig(gi), f_ = fsig(gf), g_ = ftanh(gg), o_ = fsig(go);
            cstate = f_ * cstate + i_ * g_;
            float h_ = o_ * ftanh(cstate);
            hlast = h_;
            const int kidx = 32 * r + lane;
            ull pv = (ull)__float_as_uint(h_) | ((ull)(unsigned)(t + 1) << 32);
            st_rlx(htg + (size_t)(par ^ 1) * 1024 + w * 256 + kidx, pv);
            out[((size_t)(batch0 + w) * SEQ + t) * HID + kidx] = h_;

            // ---- speculative polls for t+1 ----
            const ull* sp = htg + (size_t)(par ^ 1) * 1024 + bb * 256 + kown;
            sv0 = ld_rlx(sp); sv1 = ld_rlx(sp + 256);
        }
        p3 = (p3 == 2) ? 0 : p3 + 1;
    }

    // ---- h_n (second output region) ----
    if (isact && out_size >= (long long)BATCH * SEQ * HID + BATCH * HID) {
        out[(size_t)BATCH * SEQ * HID + (size_t)(batch0 + w) * HID + 32 * r + lane] = hlast;
    }
}

// ============================================================
__global__ __launch_bounds__(THREADS, 1)
void lstm_kernel(float* __restrict__ out,
                 const float* __restrict__ x,
                 const float* __restrict__ WX,
                 const float* __restrict__ WH,
                 const float* __restrict__ BX,
                 const float* __restrict__ BH,
                 long long out_size)
{
    extern __shared__ char smem[];
    if (blockIdx.x >= NWORK) {
        if (threadIdx.x < 256) helper_body(blockIdx.x - NWORK, x, WX, smem);
    } else {
        worker_body(out, x, WX, WH, BX, BH, out_size, smem);
    }
}

// ============================================================
extern "C" void kernel_launch(void* const* d_in, const int* in_sizes, int n_in,
                              void* d_out, int out_size)
{
    const float* x  = (const float*)d_in[0];
    const float* WX = (const float*)d_in[1];
    const float* WH = (const float*)d_in[2];
    const float* BX = (const float*)d_in[3];
    const float* BH = (const float*)d_in[4];
    float* out = (float*)d_out;

    const size_t smem_bytes = 98304 + 8192 + 8192 + 98304 + 2048;  // 215040
    cudaFuncSetAttribute(lstm_kernel, cudaFuncAttributeMaxDynamicSharedMemorySize,
                         (int)smem_bytes);

    init_kernel<<<64, 256>>>();
    lstm_kernel<<<NWORK + NHELP, THREADS, smem_bytes>>>(
        out, x, WX, WH, BX, BH, (long long)out_size);
}

// round 13
// speedup vs baseline: 1.4316x; 1.0022x over previous
#include <cuda_runtime.h>
#include <stdint.h>

typedef unsigned long long ull;

// ---------- f32x2 packed-fp32 helpers ----------
__device__ __forceinline__ ull pk2(float lo, float hi) {
    ull r; asm("mov.b64 %0,{%1,%2};" : "=l"(r) : "f"(lo), "f"(hi)); return r;
}
__device__ __forceinline__ void upk2(ull v, float& lo, float& hi) {
    asm("mov.b64 {%0,%1},%2;" : "=f"(lo), "=f"(hi) : "l"(v));
}
__device__ __forceinline__ ull ffma2(ull a, ull b, ull c) {
    ull d; asm("fma.rn.f32x2 %0,%1,%2,%3;" : "=l"(d) : "l"(a), "l"(b), "l"(c)); return d;
}
__device__ __forceinline__ ull fadd2(ull a, ull b) {
    ull d; asm("add.rn.f32x2 %0,%1,%2;" : "=l"(d) : "l"(a), "l"(b)); return d;
}

// ---------- L2 sync primitives ----------
__device__ __forceinline__ ull ld_rlx(const ull* p) {
    ull v;
    asm volatile("ld.relaxed.gpu.global.u64 %0, [%1];" : "=l"(v) : "l"(p) : "memory");
    return v;
}
__device__ __forceinline__ void st_rlx(ull* p, ull v) {
    asm volatile("st.relaxed.gpu.global.u64 [%0], %1;" :: "l"(p), "l"(v) : "memory");
}
__device__ __forceinline__ unsigned ld_acq_u32(const unsigned* p) {
    unsigned v;
    asm volatile("ld.acquire.gpu.global.u32 %0, [%1];" : "=r"(v) : "l"(p) : "memory");
    return v;
}
__device__ __forceinline__ void st_rel_u32(unsigned* p, unsigned v) {
    asm volatile("st.release.gpu.global.u32 [%0], %1;" :: "l"(p), "r"(v) : "memory");
}

// ---------- problem constants ----------
#define BATCH   64
#define SEQ     2048
#define FEAT    256
#define HID     256
#define G4      1024
#define BG      4
#define NGROUP  16
#define NWORK   128
#define NHELP   20
#define THREADS 512
#define CK      16      // k per chunk; 16 chunks; warps 0-3's chunks (k<64) offloaded

// ---------- scratch ----------
__device__ ull      ht_buf[NGROUP * 2 * BG * HID];      // tagged h [grp][par][b][k]
__device__ float    xp_part[(size_t)SEQ * BATCH * G4];  // helper partials [t][b][col]
__device__ unsigned flag_buf[SEQ];

// ============================================================
__global__ void init_kernel() {
    int t = blockIdx.x * blockDim.x + threadIdx.x;
    if (t < NGROUP * 1024) {
        int grp = t >> 10, rem = t & 1023;
        ht_buf[grp * 2048 + rem] = 0ull;    // parity-0: tag 0, h=0
    }
    if (t < SEQ) flag_buf[t] = 0u;
}

// ============================================================
// Helper: 20 CTAs (threads<256) precompute xp_part over
// offK = [0,64)  (worker act-warps 0..3). Proven-sustainable load.
// ============================================================
__device__ void helper_body(int hj, const float* __restrict__ x,
                            const float* __restrict__ WX, char* smem)
{
    float (*xs)[68] = (float(*)[68])smem;
    float (*ws)[64] = (float(*)[64])(smem + 64 * 68 * 4);

    const int tid = threadIdx.x;
    const int ty = tid >> 4, tx = tid & 15;

    for (int t = hj; t < SEQ; t += NHELP) {
#pragma unroll
        for (int it = 0; it < 4; it++) {
            int f = tid + 256 * it;           // 0..1023
            int row = f >> 4, j = f & 15;
            float4 v = *(const float4*)&x[((size_t)row * SEQ + t) * FEAT + 4 * j];
            int kl = 4 * j;
            xs[kl + 0][row] = v.x; xs[kl + 1][row] = v.y;
            xs[kl + 2][row] = v.z; xs[kl + 3][row] = v.w;
        }
        for (int ct = 0; ct < 16; ct++) {
            __syncthreads();
#pragma unroll
            for (int it = 0; it < 4; it++) {
                int f2 = tid + 256 * it;
                int k = f2 >> 4, c4 = f2 & 15;
                float4 v = *(const float4*)&WX[(size_t)k * G4 + 64 * ct + 4 * c4];
                *(float4*)&ws[k][4 * c4] = v;
            }
            __syncthreads();
            ull acc[4][2];
#pragma unroll
            for (int i = 0; i < 4; i++) { acc[i][0] = pk2(0.f, 0.f); acc[i][1] = pk2(0.f, 0.f); }
#pragma unroll 16
            for (int kk = 0; kk < 64; kk++) {
                float4 a4 = *(const float4*)&xs[kk][4 * ty];
                float4 b4 = *(const float4*)&ws[kk][4 * tx];
                ull b01 = pk2(b4.x, b4.y), b23 = pk2(b4.z, b4.w);
                ull am;
                am = pk2(a4.x, a4.x); acc[0][0] = ffma2(am, b01, acc[0][0]); acc[0][1] = ffma2(am, b23, acc[0][1]);
                am = pk2(a4.y, a4.y); acc[1][0] = ffma2(am, b01, acc[1][0]); acc[1][1] = ffma2(am, b23, acc[1][1]);
                am = pk2(a4.z, a4.z); acc[2][0] = ffma2(am, b01, acc[2][0]); acc[2][1] = ffma2(am, b23, acc[2][1]);
                am = pk2(a4.w, a4.w); acc[3][0] = ffma2(am, b01, acc[3][0]); acc[3][1] = ffma2(am, b23, acc[3][1]);
            }
            size_t base = ((size_t)t * BATCH + 4 * ty) * G4 + 64 * ct + 4 * tx;
#pragma unroll
            for (int i = 0; i < 4; i++) {
                float4 o;
                upk2(acc[i][0], o.x, o.y);
                upk2(acc[i][1], o.z, o.w);
                *(float4*)&xp_part[base + (size_t)i * G4] = o;
            }
        }
        __syncthreads();
        if (tid == 0) st_rel_u32(&flag_buf[t], 1u);
        __syncthreads();
    }
}

// ============================================================
// Worker: 128 CTAs x 512 threads, WARP-SPECIALIZED step pipeline.
// Warps 0-3 (act): poll, h-GEMM k<64, stage, bar.sync, reduce+act+
//   publish (their xp offloaded to helpers).
// Warps 4-15 (gemm): poll, h-GEMM, stage, bar.ARRIVE (non-blocking),
//   then x-stage + xp-GEMM(t+1) + spec polls — overlaps act phase.
// red triple-buffered (t%3): group publish/poll chain bounds gemm
// warps to <= act+2 steps, so 3 buffers suffice; no __syncthreads
// in the loop.
// ============================================================
__device__ __forceinline__ float fsig(float x) {
    return __fdividef(1.0f, 1.0f + __expf(-x));
}
__device__ __forceinline__ float ftanh(float x) { return 2.0f * fsig(2.0f * x) - 1.0f; }

__device__ void worker_body(float* __restrict__ out,
                            const float* __restrict__ x,
                            const float* __restrict__ WX,
                            const float* __restrict__ WH,
                            const float* __restrict__ BX,
                            const float* __restrict__ BH,
                            long long out_size, char* smem)
{
    ulonglong2* wx_u2   = (ulonglong2*)smem;                 // [192][32] k=64..255  96 KB
    ull*        hd      = (ull*)(smem + 98304);              // [256][4]              8 KB
    ull*        xd      = (ull*)(smem + 106496);             // [256][4]              8 KB
    ulonglong2* red     = (ulonglong2*)(smem + 114688);      // [3][4][16][32]       96 KB
    float*      gates_s = (float*)(smem + 212992);           // [4][128]              2 KB

    const int tid = threadIdx.x;
    const int grp = blockIdx.x >> 3;
    const int r   = blockIdx.x & 7;
    const int batch0 = grp * BG;

    const int w    = tid >> 5;           // chunk 0..15
    const int lane = tid & 31;
    const int cq   = lane;
    const int kbase = CK * w;
    const int kown  = kbase + (lane & 15);
    const int bb    = (lane >> 4) << 1;
    const bool isact = (w < 4);          // warps 0-3: act duty; xp offloaded

    // ---- WX slice (k 64..255) into SMEM, pre-packed ----
    for (int idx = tid; idx < 192 * 32; idx += THREADS) {
        int f = idx >> 5, ci = idx & 31;
        int gcl = (ci >> 3) * HID + 32 * r + ((4 * ci) & 31);
        float4 w4 = *(const float4*)&WX[(size_t)(64 + f) * G4 + gcl];
        wx_u2[idx] = make_ulonglong2(pk2(w4.x, w4.y), pk2(w4.z, w4.w));
    }

    // ---- WH chunk into registers (all 16 warps) ----
    ull wA[CK], wB[CK];
    {
        const int gc = (cq >> 3) * HID + 32 * r + ((4 * cq) & 31);
        const float* wp = WH + (size_t)kbase * G4 + gc;
#pragma unroll
        for (int kk = 0; kk < CK; kk++) {
            float4 w4 = *(const float4*)(wp + (size_t)kk * G4);
            wA[kk] = pk2(w4.x, w4.y);
            wB[kk] = pk2(w4.z, w4.w);
        }
    }

    // ---- bias + gate-col (act warps) ----
    ull biasA = pk2(0.f, 0.f), biasB = biasA;
    int gcol = 0;
    if (isact) {
        gcol = (lane >> 3) * HID + 32 * r + ((4 * lane) & 31);
        float4 bx4 = *(const float4*)&BX[gcol];
        float4 bh4 = *(const float4*)&BH[gcol];
        biasA = pk2(bx4.x + bh4.x, bx4.y + bh4.y);
        biasB = pk2(bx4.z + bh4.z, bx4.w + bh4.w);
    }

    // ---- x feeds (gemm warps only; k 64..255) ----
    const float* xb0 = x + ((size_t)(batch0 + bb) * SEQ) * FEAT + kown;
    const float* xb1 = xb0 + (size_t)SEQ * FEAT;
    float xr0 = 0.f, xr1 = 0.f;
    if (!isact) {
        float a0 = xb0[0], a1 = xb1[0];          // x(0)
        xd[kown * BG + bb]     = pk2(a0, a0);
        xd[kown * BG + bb + 1] = pk2(a1, a1);
        xr0 = xb0[FEAT];                          // x(1)
        xr1 = xb1[FEAT];
    }
    __syncthreads();   // wx_s + xd(0) visible

    ull* htg = &ht_buf[(size_t)grp * 2048];       // [par][b][k]

    ull a00, a01, a10, a11, a20, a21, a30, a31;
    a00 = a01 = a10 = a11 = a20 = a21 = a30 = a31 = pk2(0.f, 0.f);
    if (!isact) {   // prologue xp-GEMM(0)
        const ull* xp_ = xd + kbase * BG;
        const ulonglong2* wp = wx_u2 + (kbase - 64) * 32 + cq;
#pragma unroll
        for (int kk = 0; kk < CK; kk++) {
            ulonglong2 d0 = *(const ulonglong2*)(xp_ + kk * 4);
            ulonglong2 d1 = *(const ulonglong2*)(xp_ + kk * 4 + 2);
            ulonglong2 w2 = wp[kk * 32];
            a00 = ffma2(d0.x, w2.x, a00); a01 = ffma2(d0.x, w2.y, a01);
            a10 = ffma2(d0.y, w2.x, a10); a11 = ffma2(d0.y, w2.y, a11);
            a20 = ffma2(d1.x, w2.x, a20); a21 = ffma2(d1.x, w2.y, a21);
            a30 = ffma2(d1.y, w2.x, a30); a31 = ffma2(d1.y, w2.y, a31);
        }
    }

    // ---- speculative preload t=0 (parity-0 zeroed: guaranteed hit) ----
    ull sv0 = ld_rlx(htg + bb * 256 + kown);
    ull sv1 = ld_rlx(htg + (bb + 1) * 256 + kown);

    float cstate = 0.0f, hlast = 0.0f;
    int p3 = 0;

    for (int t = 0; t < SEQ; t++) {
        const int par = t & 1;

        // ---- poll own slots; pack hd (warp-private) ----
        {
            const ull* sp0 = htg + (size_t)par * 1024 + bb * 256 + kown;
            const unsigned tg = (unsigned)t;
            while (((unsigned)(sv0 >> 32) != tg) | ((unsigned)(sv1 >> 32) != tg)) {
                sv0 = ld_rlx(sp0); sv1 = ld_rlx(sp0 + 256);
            }
            float h0 = __uint_as_float((unsigned)sv0);
            float h1 = __uint_as_float((unsigned)sv1);
            hd[kown * BG + bb]     = pk2(h0, h0);
            hd[kown * BG + bb + 1] = pk2(h1, h1);
        }
        __syncwarp();

        // ---- act warps: flag-gated xp_part prefetch (hides under h-GEMM) ----
        float4 xpp = make_float4(0.f, 0.f, 0.f, 0.f);
        if (isact) {
            while (ld_acq_u32(&flag_buf[t]) == 0u) { }
            xpp = __ldcg((const float4*)&xp_part[((size_t)t * BATCH + batch0 + w) * G4 + gcol]);
            a00 = a01 = a10 = a11 = a20 = a21 = a30 = a31 = pk2(0.f, 0.f);
        }

        // ---- h-GEMM chunk (all 16 warps) ----
        {
            const ull* hp = hd + kbase * BG;
#pragma unroll
            for (int kk = 0; kk < CK; kk++) {
                ulonglong2 d0 = *(const ulonglong2*)(hp + kk * 4);
                ulonglong2 d1 = *(const ulonglong2*)(hp + kk * 4 + 2);
                a00 = ffma2(d0.x, wA[kk], a00); a01 = ffma2(d0.x, wB[kk], a01);
                a10 = ffma2(d0.y, wA[kk], a10); a11 = ffma2(d0.y, wB[kk], a11);
                a20 = ffma2(d1.x, wA[kk], a20); a21 = ffma2(d1.x, wB[kk], a21);
                a30 = ffma2(d1.y, wA[kk], a30); a31 = ffma2(d1.y, wB[kk], a31);
            }
        }
        {   // stage: red[p3][b][w][cq]
            ulonglong2* rp = red + (size_t)p3 * 2048;
            rp[(0 * 16 + w) * 32 + cq] = make_ulonglong2(a00, a01);
            rp[(1 * 16 + w) * 32 + cq] = make_ulonglong2(a10, a11);
            rp[(2 * 16 + w) * 32 + cq] = make_ulonglong2(a20, a21);
            rp[(3 * 16 + w) * 32 + cq] = make_ulonglong2(a30, a31);
        }
        __syncwarp();   // all lanes past h-GEMM reads before next hd/xd writes

        if (!isact) {
            // ---- signal staging done; do NOT wait for act phase ----
            asm volatile("bar.arrive 1, 512;" ::: "memory");

            // ---- stage x(t+1), prefetch x(t+2) ----
            xd[kown * BG + bb]     = pk2(xr0, xr0);
            xd[kown * BG + bb + 1] = pk2(xr1, xr1);
            __syncwarp();
            {
                size_t tn = (size_t)((t + 2 < SEQ) ? (t + 2) : t) * FEAT;
                xr0 = xb0[tn];
                xr1 = xb1[tn];
            }

            // ---- xp-GEMM(t+1) with mid-point speculative polls ----
            a00 = a01 = a10 = a11 = a20 = a21 = a30 = a31 = pk2(0.f, 0.f);
            const ull* xp_ = xd + kbase * BG;
            const ulonglong2* wp = wx_u2 + (kbase - 64) * 32 + cq;
#pragma unroll
            for (int kk = 0; kk < 8; kk++) {
                ulonglong2 d0 = *(const ulonglong2*)(xp_ + kk * 4);
                ulonglong2 d1 = *(const ulonglong2*)(xp_ + kk * 4 + 2);
                ulonglong2 w2 = wp[kk * 32];
                a00 = ffma2(d0.x, w2.x, a00); a01 = ffma2(d0.x, w2.y, a01);
                a10 = ffma2(d0.y, w2.x, a10); a11 = ffma2(d0.y, w2.y, a11);
                a20 = ffma2(d1.x, w2.x, a20); a21 = ffma2(d1.x, w2.y, a21);
                a30 = ffma2(d1.y, w2.x, a30); a31 = ffma2(d1.y, w2.y, a31);
            }
            {   // speculative polls for t+1
                const ull* sp = htg + (size_t)(par ^ 1) * 1024 + bb * 256 + kown;
                sv0 = ld_rlx(sp); sv1 = ld_rlx(sp + 256);
            }
#pragma unroll
            for (int kk = 8; kk < CK; kk++) {
                ulonglong2 d0 = *(const ulonglong2*)(xp_ + kk * 4);
                ulonglong2 d1 = *(const ulonglong2*)(xp_ + kk * 4 + 2);
                ulonglong2 w2 = wp[kk * 32];
                a00 = ffma2(d0.x, w2.x, a00); a01 = ffma2(d0.x, w2.y, a01);
                a10 = ffma2(d0.y, w2.x, a10); a11 = ffma2(d0.y, w2.y, a11);
                a20 = ffma2(d1.x, w2.x, a20); a21 = ffma2(d1.x, w2.y, a21);
                a30 = ffma2(d1.y, w2.x, a30); a31 = ffma2(d1.y, w2.y, a31);
            }
        } else {
            // ---- wait for all 16 stagings ----
            asm volatile("bar.sync 1, 512;" ::: "memory");

            // ---- reduce 16 partials (+bias +xp_part) ----
            const ulonglong2* q = red + (size_t)p3 * 2048 + w * 512;
            ull s0 = fadd2(biasA, pk2(xpp.x, xpp.y));
            ull s1 = fadd2(biasB, pk2(xpp.z, xpp.w));
#pragma unroll
            for (int j = 0; j < 16; j++) {
                ulonglong2 v = q[j * 32 + lane];
                s0 = fadd2(s0, v.x);
                s1 = fadd2(s1, v.y);
            }
            float g0, g1, g2, g3;
            upk2(s0, g0, g1); upk2(s1, g2, g3);
            *(float4*)&gates_s[w * 128 + 4 * lane] = make_float4(g0, g1, g2, g3);
            __syncwarp();

            // ---- act + publish + archive ----
            float gi = gates_s[w * 128 +       lane];
            float gf = gates_s[w * 128 +  32 + lane];
            float gg = gates_s[w * 128 +  64 + lane];
            float go = gates_s[w * 128 +  96 + lane];
            float i_ = fsig(gi), f_ = fsig(gf), g_ = ftanh(gg), o_ = fsig(go);
            cstate = f_ * cstate + i_ * g_;
            float h_ = o_ * ftanh(cstate);
            hlast = h_;
            const int kidx = 32 * r + lane;
            ull pv = (ull)__float_as_uint(h_) | ((ull)(unsigned)(t + 1) << 32);
            st_rlx(htg + (size_t)(par ^ 1) * 1024 + w * 256 + kidx, pv);
            out[((size_t)(batch0 + w) * SEQ + t) * HID + kidx] = h_;

            // ---- speculative polls for t+1 ----
            const ull* sp = htg + (size_t)(par ^ 1) * 1024 + bb * 256 + kown;
            sv0 = ld_rlx(sp); sv1 = ld_rlx(sp + 256);
        }
        p3 = (p3 == 2) ? 0 : p3 + 1;
    }

    // ---- h_n (second output region) ----
    if (isact && out_size >= (long long)BATCH * SEQ * HID + BATCH * HID) {
        out[(size_t)BATCH * SEQ * HID + (size_t)(batch0 + w) * HID + 32 * r + lane] = hlast;
    }
}

// ============================================================
__global__ __launch_bounds__(THREADS, 1)
void lstm_kernel(float* __restrict__ out,
                 const float* __restrict__ x,
                 const float* __restrict__ WX,
                 const float* __restrict__ WH,
                 const float* __restrict__ BX,
                 const float* __restrict__ BH,
                 long long out_size)
{
    extern __shared__ char smem[];
    if (blockIdx.x >= NWORK) {
        if (threadIdx.x < 256) helper_body(blockIdx.x - NWORK, x, WX, smem);
    } else {
        worker_body(out, x, WX, WH, BX, BH, out_size, smem);
    }
}

// ============================================================
extern "C" void kernel_launch(void* const* d_in, const int* in_sizes, int n_in,
                              void* d_out, int out_size)
{
    const float* x  = (const float*)d_in[0];
    const float* WX = (const float*)d_in[1];
    const float* WH = (const float*)d_in[2];
    const float* BX = (const float*)d_in[3];
    const float* BH = (const float*)d_in[4];
    float* out = (float*)d_out;

    const size_t smem_bytes = 98304 + 8192 + 8192 + 98304 + 2048;  // 215040
    cudaFuncSetAttribute(lstm_kernel, cudaFuncAttributeMaxDynamicSharedMemorySize,
                         (int)smem_bytes);

    init_kernel<<<64, 256>>>();
    lstm_kernel<<<NWORK + NHELP, THREADS, smem_bytes>>>(
        out, x, WX, WH, BX, BH, (long long)out_size);
}

// round 15
// speedup vs baseline: 1.5222x; 1.0633x over previous
#include <cuda_runtime.h>
#include <stdint.h>

typedef unsigned long long ull;

__device__ __forceinline__ ull pk2(float lo, float hi) {
    ull r; asm("mov.b64 %0,{%1,%2};" : "=l"(r) : "f"(lo), "f"(hi)); return r;
}
__device__ __forceinline__ void upk2(ull v, float& lo, float& hi) {
    asm("mov.b64 {%0,%1},%2;" : "=f"(lo), "=f"(hi) : "l"(v));
}
__device__ __forceinline__ ull ffma2(ull a, ull b, ull c) {
    ull d; asm("fma.rn.f32x2 %0,%1,%2,%3;" : "=l"(d) : "l"(a), "l"(b), "l"(c)); return d;
}
__device__ __forceinline__ ull fadd2(ull a, ull b) {
    ull d; asm("add.rn.f32x2 %0,%1,%2;" : "=l"(d) : "l"(a), "l"(b)); return d;
}
__device__ __forceinline__ ull ld_rlx(const ull* p) {
    ull v; asm volatile("ld.relaxed.gpu.global.u64 %0, [%1];" : "=l"(v) : "l"(p) : "memory"); return v;
}
__device__ __forceinline__ void st_rlx(ull* p, ull v) {
    asm volatile("st.relaxed.gpu.global.u64 [%0], %1;" :: "l"(p), "l"(v) : "memory");
}
__device__ __forceinline__ unsigned ld_acq_u32(const unsigned* p) {
    unsigned v; asm volatile("ld.acquire.gpu.global.u32 %0, [%1];" : "=r"(v) : "l"(p) : "memory"); return v;
}
__device__ __forceinline__ void st_rel_u32(unsigned* p, unsigned v) {
    asm volatile("st.release.gpu.global.u32 [%0], %1;" :: "l"(p), "r"(v) : "memory");
}

#define BATCH   64
#define SEQ     2048
#define FEAT    256
#define HID     256
#define G4      1024
#define BG      4
#define NGROUP  16
#define NWORK   128
#define NHELP   20

__device__ ull      ht_buf[NGROUP * 2 * BG * HID];      // tagged h [grp][par][b][k]
__device__ float    xp_part[(size_t)SEQ * BATCH * G4];  // helper partials [t][b][col]
__device__ unsigned flag_buf[SEQ];

// ============================================================
__global__ void init_kernel() {
    int t = blockIdx.x * blockDim.x + threadIdx.x;
    if (t < NGROUP * 1024) {
        int grp = t >> 10, rem = t & 1023;
        ht_buf[grp * 2048 + rem] = 0ull;    // parity-0: tag 0, h=0
    }
    if (t < SEQ) flag_buf[t] = 0u;
}

// ============================================================
// Helper (FROZEN from R9): 20 CTAs precompute xp_part over
// offK = [64,96) U [192,224)  (worker warps 2 and 6).
// ============================================================
__device__ void helper_body(int hj, const float* __restrict__ x,
                            const float* __restrict__ WX, char* smem)
{
    float (*xs)[68] = (float(*)[68])smem;
    float (*ws)[64] = (float(*)[64])(smem + 64 * 68 * 4);

    const int tid = threadIdx.x;
    const int ty = tid >> 4, tx = tid & 15;

    for (int t = hj; t < SEQ; t += NHELP) {
#pragma unroll
        for (int it = 0; it < 4; it++) {
            int f = tid + 256 * it;
            int row = f >> 4, j = f & 15;
            int kg = (j < 8) ? (64 + 4 * j) : (192 + 4 * (j - 8));
            float4 v = *(const float4*)&x[((size_t)row * SEQ + t) * FEAT + kg];
            int kl = 4 * j;
            xs[kl + 0][row] = v.x; xs[kl + 1][row] = v.y;
            xs[kl + 2][row] = v.z; xs[kl + 3][row] = v.w;
        }
        for (int ct = 0; ct < 16; ct++) {
            __syncthreads();
#pragma unroll
            for (int it = 0; it < 4; it++) {
                int f2 = tid + 256 * it;
                int k = f2 >> 4, c4 = f2 & 15;
                int kg = (k < 32) ? (64 + k) : (192 + (k - 32));
                float4 v = *(const float4*)&WX[(size_t)kg * G4 + 64 * ct + 4 * c4];
                *(float4*)&ws[k][4 * c4] = v;
            }
            __syncthreads();
            ull acc[4][2];
#pragma unroll
            for (int i = 0; i < 4; i++) { acc[i][0] = pk2(0.f, 0.f); acc[i][1] = pk2(0.f, 0.f); }
#pragma unroll 16
            for (int kk = 0; kk < 64; kk++) {
                float4 a4 = *(const float4*)&xs[kk][4 * ty];
                float4 b4 = *(const float4*)&ws[kk][4 * tx];
                ull b01 = pk2(b4.x, b4.y), b23 = pk2(b4.z, b4.w);
                ull am;
                am = pk2(a4.x, a4.x); acc[0][0] = ffma2(am, b01, acc[0][0]); acc[0][1] = ffma2(am, b23, acc[0][1]);
                am = pk2(a4.y, a4.y); acc[1][0] = ffma2(am, b01, acc[1][0]); acc[1][1] = ffma2(am, b23, acc[1][1]);
                am = pk2(a4.z, a4.z); acc[2][0] = ffma2(am, b01, acc[2][0]); acc[2][1] = ffma2(am, b23, acc[2][1]);
                am = pk2(a4.w, a4.w); acc[3][0] = ffma2(am, b01, acc[3][0]); acc[3][1] = ffma2(am, b23, acc[3][1]);
            }
            size_t base = ((size_t)t * BATCH + 4 * ty) * G4 + 64 * ct + 4 * tx;
#pragma unroll
            for (int i = 0; i < 4; i++) {
                float4 o;
                upk2(acc[i][0], o.x, o.y);
                upk2(acc[i][1], o.z, o.w);
                *(float4*)&xp_part[base + (size_t)i * G4] = o;
            }
        }
        __syncthreads();
        if (tid == 0) st_rel_u32(&flag_buf[t], 1u);
        __syncthreads();
    }
}

// ============================================================
// Worker: R9 structure; CHANGE: hd/xd hold plain float4 per k
// (16B, 4 batches) — (h,h) duplication moved into registers
// (ALU movs ride under the FMA ceiling). Halves broadcast-read
// and staging LDS wavefronts.
// ============================================================
__device__ __forceinline__ float fsig(float v) { return __fdividef(1.0f, 1.0f + __expf(-v)); }
__device__ __forceinline__ float ftanh(float v) { return 2.0f * fsig(2.0f * v) - 1.0f; }

__device__ void worker_body(float* __restrict__ out,
                            const float* __restrict__ x,
                            const float* __restrict__ WX,
                            const float* __restrict__ WH,
                            const float* __restrict__ BX,
                            const float* __restrict__ BH,
                            long long out_size, char* smem)
{
    ulonglong2* wx_u2   = (ulonglong2*)smem;                  // [256][32]   128 KB
    float4*     hdf     = (float4*)(smem + 131072);           // [256]         4 KB
    float4*     xdf     = (float4*)(smem + 131072 + 4096);    // [2][256]      8 KB
    ulonglong2* red_u   = (ulonglong2*)(smem + 131072 + 12288);   // [2][4][256] 32 KB
    float*      gates_s = (float*)(smem + 131072 + 12288 + 32768); // [4][128]   2 KB

    const int tid = threadIdx.x;
    const int grp = blockIdx.x >> 3;
    const int r   = blockIdx.x & 7;
    const int batch0 = grp * BG;

    const int ks = tid >> 5;
    const int cq = tid & 31;
    const int rb = tid >> 5;     // act batch (tid<128)
    const int rc = tid & 31;
    const bool xact = (ks != 2 && ks != 6);   // warps 2,6 offloaded to helpers

    // ---- WX slice into SMEM, pre-packed ----
    for (int idx = tid; idx < 256 * 32; idx += 256) {
        int f = idx >> 5, ci = idx & 31;
        int gc = (ci >> 3) * HID + 32 * r + ((4 * ci) & 31);
        float4 w4 = *(const float4*)&WX[(size_t)f * G4 + gc];
        wx_u2[idx] = make_ulonglong2(pk2(w4.x, w4.y), pk2(w4.z, w4.w));
    }

    // ---- WH slice into registers ----
    ull wA[32], wB[32];
    {
        const int gc = (cq >> 3) * HID + 32 * r + ((4 * cq) & 31);
        const float* wp = WH + (size_t)(32 * ks) * G4 + gc;
#pragma unroll
        for (int kk = 0; kk < 32; kk++) {
            float4 w4 = *(const float4*)(wp + (size_t)kk * G4);
            wA[kk] = pk2(w4.x, w4.y);
            wB[kk] = pk2(w4.z, w4.w);
        }
    }

    // ---- bias + xp column ----
    ull biasA = pk2(0.f, 0.f), biasB = biasA;
    int gcol = 0;
    if (tid < 128) {
        gcol = (rc >> 3) * HID + 32 * r + ((4 * rc) & 31);
        float4 bx4 = *(const float4*)&BX[gcol];
        float4 bh4 = *(const float4*)&BH[gcol];
        biasA = pk2(bx4.x + bh4.x, bx4.y + bh4.y);
        biasB = pk2(bx4.z + bh4.z, bx4.w + bh4.w);
    }

    // ---- x prefetch: thread owns feat=tid, 4 batches (xact warps) ----
    const float* xp0 = x + (size_t)batch0 * SEQ * FEAT + tid;
    float xr0 = 0.f, xr1 = 0.f, xr2 = 0.f, xr3 = 0.f;
    if (xact) {
        xdf[tid] = make_float4(xp0[0 * (size_t)SEQ * FEAT],
                               xp0[1 * (size_t)SEQ * FEAT],
                               xp0[2 * (size_t)SEQ * FEAT],
                               xp0[3 * (size_t)SEQ * FEAT]);   // x(0) -> xd[0]
        xr0 = xp0[(size_t)1 * FEAT + 0 * (size_t)SEQ * FEAT];
        xr1 = xp0[(size_t)1 * FEAT + 1 * (size_t)SEQ * FEAT];
        xr2 = xp0[(size_t)1 * FEAT + 2 * (size_t)SEQ * FEAT];
        xr3 = xp0[(size_t)1 * FEAT + 3 * (size_t)SEQ * FEAT];
    }
    __syncthreads();

    ull* ht = &ht_buf[(size_t)grp * 2 * HID * BG];   // [par][k][b]

    ull a00, a01, a10, a11, a20, a21, a30, a31;
    a00 = a01 = a10 = a11 = a20 = a21 = a30 = a31 = pk2(0.f, 0.f);
    if (xact) {   // prologue xp-GEMM(0)
        const float4* xp_ = xdf + ks * 32;
        const ulonglong2* wp = wx_u2 + (size_t)(ks * 32) * 32 + cq;
#pragma unroll
        for (int kk = 0; kk < 32; kk++) {
            float4 xv = xp_[kk];
            ulonglong2 w2 = wp[kk * 32];
            ull m;
            m = pk2(xv.x, xv.x); a00 = ffma2(m, w2.x, a00); a01 = ffma2(m, w2.y, a01);
            m = pk2(xv.y, xv.y); a10 = ffma2(m, w2.x, a10); a11 = ffma2(m, w2.y, a11);
            m = pk2(xv.z, xv.z); a20 = ffma2(m, w2.x, a20); a21 = ffma2(m, w2.y, a21);
            m = pk2(xv.w, xv.w); a30 = ffma2(m, w2.x, a30); a31 = ffma2(m, w2.y, a31);
        }
    }

    // ---- speculative preload t=0 (parity-0 zeroed: guaranteed hit) ----
    ull sv0, sv1, sv2, sv3;
    {
        const ull* sp = ht + (size_t)tid * BG;
        sv0 = ld_rlx(sp + 0); sv1 = ld_rlx(sp + 1);
        sv2 = ld_rlx(sp + 2); sv3 = ld_rlx(sp + 3);
    }

    float cstate = 0.0f, hlast = 0.0f;

    for (int t = 0; t < SEQ; t++) {
        const int par = t & 1;

        // ---- stage x(t+1) -> xdf[par^1] ----
        if (xact) {
            xdf[(par ^ 1) * 256 + tid] = make_float4(xr0, xr1, xr2, xr3);
        }

        // ---- check speculative polls; re-poll on miss ----
        {
            const ull* sp = ht + ((size_t)par * HID + tid) * BG;
            const unsigned tg = (unsigned)t;
            while (((unsigned)(sv0 >> 32) != tg) | ((unsigned)(sv1 >> 32) != tg) |
                   ((unsigned)(sv2 >> 32) != tg) | ((unsigned)(sv3 >> 32) != tg)) {
                sv0 = ld_rlx(sp + 0); sv1 = ld_rlx(sp + 1);
                sv2 = ld_rlx(sp + 2); sv3 = ld_rlx(sp + 3);
            }
            hdf[tid] = make_float4(__uint_as_float((unsigned)sv0),
                                   __uint_as_float((unsigned)sv1),
                                   __uint_as_float((unsigned)sv2),
                                   __uint_as_float((unsigned)sv3));
        }
        __syncwarp();

        // ---- flag-gated xp_part prefetch (hides under h-GEMM) ----
        float4 xpp = make_float4(0.f, 0.f, 0.f, 0.f);
        if (tid < 128) {
            while (ld_acq_u32(&flag_buf[t]) == 0u) { }
            xpp = __ldcg((const float4*)&xp_part[((size_t)t * BATCH + batch0 + rb) * G4 + gcol]);
        }

        // ---- h-GEMM chunk: broadcast f4 read + dup-in-regs ----
        {
            const float4* hp = hdf + ks * 32;
#pragma unroll
            for (int kk = 0; kk < 32; kk++) {
                float4 hv = hp[kk];
                ull m;
                m = pk2(hv.x, hv.x); a00 = ffma2(m, wA[kk], a00); a01 = ffma2(m, wB[kk], a01);
                m = pk2(hv.y, hv.y); a10 = ffma2(m, wA[kk], a10); a11 = ffma2(m, wB[kk], a11);
                m = pk2(hv.z, hv.z); a20 = ffma2(m, wA[kk], a20); a21 = ffma2(m, wB[kk], a21);
                m = pk2(hv.w, hv.w); a30 = ffma2(m, wA[kk], a30); a31 = ffma2(m, wB[kk], a31);
            }
        }
        {
            ulonglong2* rp = red_u + (size_t)par * 1024;
            rp[0 * 256 + tid] = make_ulonglong2(a00, a01);
            rp[1 * 256 + tid] = make_ulonglong2(a10, a11);
            rp[2 * 256 + tid] = make_ulonglong2(a20, a21);
            rp[3 * 256 + tid] = make_ulonglong2(a30, a31);
        }
        __syncthreads();

        // ---- reduce (+bias +xp) -> act -> publish ----
        if (tid < 128) {
            const ulonglong2* q = red_u + ((size_t)par * 4 + rb) * 256;
            ull s0 = fadd2(biasA, pk2(xpp.x, xpp.y));
            ull s1 = fadd2(biasB, pk2(xpp.z, xpp.w));
#pragma unroll
            for (int j = 0; j < 8; j++) {
                ulonglong2 v = q[j * 32 + rc];
                s0 = fadd2(s0, v.x); s1 = fadd2(s1, v.y);
            }
            float g0, g1, g2, g3;
            upk2(s0, g0, g1); upk2(s1, g2, g3);
            *(float4*)&gates_s[rb * 128 + 4 * rc] = make_float4(g0, g1, g2, g3);
        }
        __syncwarp();
        if (tid < 128) {
            float gi = gates_s[rb * 128 +      rc];
            float gf = gates_s[rb * 128 + 32 + rc];
            float gg = gates_s[rb * 128 + 64 + rc];
            float go = gates_s[rb * 128 + 96 + rc];
            float i_ = fsig(gi), f_ = fsig(gf), g_ = ftanh(gg), o_ = fsig(go);
            cstate = f_ * cstate + i_ * g_;
            float h_ = o_ * ftanh(cstate);
            hlast = h_;
            const int kidx = 32 * r + rc;
            ull pv = (ull)__float_as_uint(h_) | ((ull)(unsigned)(t + 1) << 32);
            st_rlx(ht + ((size_t)((t + 1) & 1) * HID + kidx) * BG + rb, pv);
            out[((size_t)(batch0 + rb) * SEQ + t) * HID + kidx] = h_;
        }

        // ---- prefetch x(t+2) ----
        if (xact) {
            size_t tn = (size_t)((t + 2 < SEQ) ? (t + 2) : t) * FEAT;
            xr0 = xp0[tn + 0 * (size_t)SEQ * FEAT];
            xr1 = xp0[tn + 1 * (size_t)SEQ * FEAT];
            xr2 = xp0[tn + 2 * (size_t)SEQ * FEAT];
            xr3 = xp0[tn + 3 * (size_t)SEQ * FEAT];
        }

        // ---- xp-GEMM(t+1) with mid-point speculative polls ----
        a00 = a01 = a10 = a11 = a20 = a21 = a30 = a31 = pk2(0.f, 0.f);
        if (xact) {
            const float4* xp_ = xdf + (par ^ 1) * 256 + ks * 32;
            const ulonglong2* wp = wx_u2 + (size_t)(ks * 32) * 32 + cq;
#pragma unroll
            for (int kk = 0; kk < 16; kk++) {
                float4 xv = xp_[kk];
                ulonglong2 w2 = wp[kk * 32];
                ull m;
                m = pk2(xv.x, xv.x); a00 = ffma2(m, w2.x, a00); a01 = ffma2(m, w2.y, a01);
                m = pk2(xv.y, xv.y); a10 = ffma2(m, w2.x, a10); a11 = ffma2(m, w2.y, a11);
                m = pk2(xv.z, xv.z); a20 = ffma2(m, w2.x, a20); a21 = ffma2(m, w2.y, a21);
                m = pk2(xv.w, xv.w); a30 = ffma2(m, w2.x, a30); a31 = ffma2(m, w2.y, a31);
            }
            {   // speculative polls for t+1
                const ull* sp = ht + ((size_t)((t + 1) & 1) * HID + tid) * BG;
                sv0 = ld_rlx(sp + 0); sv1 = ld_rlx(sp + 1);
                sv2 = ld_rlx(sp + 2); sv3 = ld_rlx(sp + 3);
            }
#pragma unroll
            for (int kk = 16; kk < 32; kk++) {
                float4 xv = xp_[kk];
                ulonglong2 w2 = wp[kk * 32];
                ull m;
                m = pk2(xv.x, xv.x); a00 = ffma2(m, w2.x, a00); a01 = ffma2(m, w2.y, a01);
                m = pk2(xv.y, xv.y); a10 = ffma2(m, w2.x, a10); a11 = ffma2(m, w2.y, a11);
                m = pk2(xv.z, xv.z); a20 = ffma2(m, w2.x, a20); a21 = ffma2(m, w2.y, a21);
                m = pk2(xv.w, xv.w); a30 = ffma2(m, w2.x, a30); a31 = ffma2(m, w2.y, a31);
            }
        } else {
            const ull* sp = ht + ((size_t)((t + 1) & 1) * HID + tid) * BG;
            sv0 = ld_rlx(sp + 0); sv1 = ld_rlx(sp + 1);
            sv2 = ld_rlx(sp + 2); sv3 = ld_rlx(sp + 3);
        }
    }

    if (tid < 128 && out_size >= (long long)BATCH * SEQ * HID + BATCH * HID)
        out[(size_t)BATCH * SEQ * HID + (size_t)(batch0 + rb) * HID + 32 * r + rc] = hlast;
}

// ============================================================
__global__ __launch_bounds__(256, 1)
void lstm_kernel(float* __restrict__ out, const float* __restrict__ x,
                 const float* __restrict__ WX, const float* __restrict__ WH,
                 const float* __restrict__ BX, const float* __restrict__ BH,
                 long long out_size)
{
    extern __shared__ char smem[];
    if (blockIdx.x >= NWORK) helper_body(blockIdx.x - NWORK, x, WX, smem);
    else worker_body(out, x, WX, WH, BX, BH, out_size, smem);
}

// ============================================================
extern "C" void kernel_launch(void* const* d_in, const int* in_sizes, int n_in,
                              void* d_out, int out_size)
{
    const float* x  = (const float*)d_in[0];
    const float* WX = (const float*)d_in[1];
    const float* WH = (const float*)d_in[2];
    const float* BX = (const float*)d_in[3];
    const float* BH = (const float*)d_in[4];
    float* out = (float*)d_out;

    const size_t smem_bytes = 131072 + 4096 + 8192 + 32768 + 2048;  // 178176
    cudaFuncSetAttribute(lstm_kernel, cudaFuncAttributeMaxDynamicSharedMemorySize,
                         (int)smem_bytes);

    init_kernel<<<64, 256>>>();
    lstm_kernel<<<NWORK + NHELP, 256, smem_bytes>>>(
        out, x, WX, WH, BX, BH, (long long)out_size);
}